// round 16
// baseline (speedup 1.0000x reference)
#include <cuda_runtime.h>

#define D_      64
#define K_      16
#define N_      65536
#define P_      2
#define NOISEF  0.1f
#define LOG2PI_F 1.83787706640934534f

#define NBLK    296            // 2 CTAs x 148 SMs, all co-resident
#define TROWS   32
#define SXST    72             // padded row stride: conflict-free fragment LDS
#define WST     20             // padded row stride for 64x16 arrays
#define PSTRIDE (2 * TROWS * SXST)   // floats per 64-row buffer (4608)
#define DYNSMEM (3 * PSTRIDE * 4)    // 55296 bytes
#define LST     68             // Va/Vb row stride (16B-aligned)

__device__ float    g_Cf[D_ * D_];
__device__ float    g_Lam[D_ * D_];
__device__ float    g_part[D_ * P_];
__device__ unsigned g_done;      // xtx completion counter (-> 296)
__device__ unsigned g_doneL;     // Lambda completion counter (-> 128)

__device__ __forceinline__ void cpasync16(unsigned smem, const void* g) {
    asm volatile("cp.async.cg.shared.global [%0], [%1], 16;\n" :: "r"(smem), "l"(g));
}
__device__ __forceinline__ void cp_commit() {
    asm volatile("cp.async.commit_group;\n" ::: "memory");
}
__device__ __forceinline__ void cp_wait1() {
    asm volatile("cp.async.wait_group 1;\n" ::: "memory");
}
__device__ __forceinline__ unsigned cvt_tf32(float f) {
    unsigned r;
    asm("cvt.rna.tf32.f32 %0, %1;" : "=r"(r) : "f"(f));
    return r;
}
__device__ __forceinline__ void mma_tf32(float& d0, float& d1, float& d2, float& d3,
                                         unsigned a0, unsigned a1, unsigned a2, unsigned a3,
                                         unsigned b0, unsigned b1) {
    asm("mma.sync.aligned.m16n8k8.row.col.f32.tf32.tf32.f32 "
        "{%0,%1,%2,%3}, {%4,%5,%6,%7}, {%8,%9}, {%0,%1,%2,%3};"
        : "+f"(d0), "+f"(d1), "+f"(d2), "+f"(d3)
        : "r"(a0), "r"(a1), "r"(a2), "r"(a3), "r"(b0), "r"(b1));
}
__device__ __forceinline__ unsigned ld_acq(unsigned* p) {
    unsigned v;
    asm volatile("ld.acquire.gpu.u32 %0, [%1];" : "=r"(v) : "l"(p) : "memory");
    return v;
}
__device__ __forceinline__ void red2(float* p, float a, float b) {
    asm volatile("red.global.add.v2.f32 [%0], {%1, %2};" :: "l"(p), "f"(a), "f"(b) : "memory");
}

// ---------------------------------------------------------------------------
// Linear-functional formulation: total = sum_task A0_task - (0.5/N) tr(Lam C).
// Lam and A0 are C-INDEPENDENT -> computed by pair blocks in the shadow of
// phase 1 and red2-accumulated. Only ONE finalizer block touches C after the
// device barrier (4096-element dot product). The 15us pairs tail is gone.
// ---------------------------------------------------------------------------
__global__ __launch_bounds__(256, 2) void k_fused(const float* __restrict__ x,
                                                  const float* __restrict__ W,
                                                  const int* __restrict__ perms,
                                                  float* __restrict__ out) {
    extern __shared__ __align__(16) float s_dyn[];   // phase1 tiles / Va,Vb
    __shared__ __align__(16) float s_wm[D_ * WST];
    __shared__ __align__(16) float s_B[D_ * 17];
    __shared__ float s_inv[D_];
    __shared__ float s_g[K_ * K_];
    __shared__ float s_gi[K_ * K_];
    __shared__ int   s_perm[D_];
    __shared__ int   s_pos[D_];
    __shared__ float s_red[2];
    __shared__ double s_tr[8];
    __shared__ double s_a0[4];
    __shared__ int   s_last;

    const int tid = threadIdx.x;

    // ---------------- Chunk schedule (pairs: 3 tiles; others: 4 or 3) ------
    int pidx = -1;
    if (blockIdx.x < 64)                            pidx = blockIdx.x;
    else if (blockIdx.x >= 148 && blockIdx.x < 212) pidx = 64 + (blockIdx.x - 148);
    int start, cnt;
    if (pidx >= 0) { start = 3 * pidx; cnt = 3; }
    else {
        int q = (blockIdx.x < 148) ? (blockIdx.x - 64) : (blockIdx.x - 128);
        if (q < 136) { start = 384 + 4 * q; cnt = 4; }
        else         { start = 928 + 3 * (q - 136); cnt = 3; }
    }

    // ---------------- Phase 1: tf32 MMA x^T x (R13-proven) ----------------
    {
        const int w    = tid >> 5;
        const int lane = tid & 31;
        const int gid  = lane >> 2;
        const int tig  = lane & 3;
        const int ms   = (w >> 1) << 4;
        const int nh   = (w & 1) << 5;

        float acc[4][4];
#pragma unroll
        for (int t = 0; t < 4; ++t)
#pragma unroll
            for (int q = 0; q < 4; ++q) acc[t][q] = 0.f;

        unsigned pb[3];
#pragma unroll
        for (int s = 0; s < 3; ++s)
            pb[s] = (unsigned)__cvta_generic_to_shared(&s_dyn[s * PSTRIDE]);

        unsigned soff[4];
#pragma unroll
        for (int i = 0; i < 4; ++i) {
            int f = tid + 256 * i;
            soff[i] = (unsigned)((f >> 4) * SXST * 4 + (f & 15) * 16);
        }

#pragma unroll
        for (int s = 0; s < 2; ++s) {
            if (s < cnt) {
                const float4* g4 = reinterpret_cast<const float4*>(
                    x + (long long)(start + s) * (2 * TROWS * 64));
#pragma unroll
                for (int i = 0; i < 4; ++i)
                    cpasync16(pb[s] + soff[i], g4 + tid + 256 * i);
            }
            cp_commit();
        }

        for (int it = 0; it < cnt; ++it) {
            const int bi = it - (it / 3) * 3;
            cp_wait1();
            __syncthreads();

            const int nxt = it + 2;
            const int nb  = (bi + 2) - ((bi + 2) / 3) * 3;
            if (nxt < cnt) {
                const float4* g4 = reinterpret_cast<const float4*>(
                    x + (long long)(start + nxt) * (2 * TROWS * 64));
#pragma unroll
                for (int i = 0; i < 4; ++i)
                    cpasync16(pb[nb] + soff[i], g4 + tid + 256 * i);
            }
            cp_commit();

            const float* buf = &s_dyn[bi * PSTRIDE];
#pragma unroll
            for (int ks = 0; ks < 8; ++ks) {
                const float* r0 = buf + (ks * 8 + tig) * SXST;
                const float* r4 = r0 + 4 * SXST;
                unsigned a0 = cvt_tf32(r0[ms + gid]);
                unsigned a1 = cvt_tf32(r0[ms + gid + 8]);
                unsigned a2 = cvt_tf32(r4[ms + gid]);
                unsigned a3 = cvt_tf32(r4[ms + gid + 8]);
#pragma unroll
                for (int t = 0; t < 4; ++t) {
                    int n0 = nh + t * 8;
                    unsigned b0 = cvt_tf32(r0[n0 + gid]);
                    unsigned b1 = cvt_tf32(r4[n0 + gid]);
                    mma_tf32(acc[t][0], acc[t][1], acc[t][2], acc[t][3],
                             a0, a1, a2, a3, b0, b1);
                }
            }
        }

#pragma unroll
        for (int t = 0; t < 4; ++t) {
            int c0 = nh + t * 8 + 2 * tig;
            red2(&g_Cf[(ms + gid) * 64 + c0],     acc[t][0], acc[t][1]);
            red2(&g_Cf[(ms + gid + 8) * 64 + c0], acc[t][2], acc[t][3]);
        }
        __threadfence();
        __syncthreads();
        if (tid == 0) atomicAdd(&g_done, 1u);
    }

    if (pidx < 0) return;
    const int task = pidx;
    const int a = task >> 1;
    const int m = a + 1;
    const int* perm = perms + (a * P_ + (task & 1)) * D_;

    // ---------------- C-independent: prep, G, Ginv, b, v, A0 ----------------
    if (tid < D_) s_perm[tid] = perm[tid];
    __syncthreads();
    if (tid < D_) s_pos[s_perm[tid]] = tid;
    __syncthreads();
#pragma unroll
    for (int i = 0; i < 4; ++i) {
        int idx = tid + 256 * i;
        int o = idx >> 4, k = idx & 15;
        float wv = W[idx];
        s_wm[o * WST + k] = (s_pos[o] >= m) ? wv : 0.f;
    }
    __syncthreads();

    const int gk = tid >> 4, gl = tid & 15;
    {
        float s = (gk == gl) ? NOISEF : 0.f;
#pragma unroll
        for (int o = 0; o < D_; ++o)
            s += s_wm[o * WST + gk] * s_wm[o * WST + gl];
        s_g[gk * K_ + gl] = s;
    }
    __syncthreads();

    if (tid < 32) {
        const int lane = tid;
        float col[K_];
#pragma unroll
        for (int r = 0; r < K_; ++r)
            col[r] = (lane < K_) ? s_g[r * K_ + lane]
                                 : ((r == lane - K_) ? 1.f : 0.f);
#pragma unroll
        for (int k = 0; k < K_; ++k) {
            float pv = __shfl_sync(0xffffffffu, col[k], k);
            float ip = 1.0f / pv;
            float ck = col[k];
#pragma unroll
            for (int r = 0; r < K_; ++r) {
                if (r != k) {
                    float mr = __shfl_sync(0xffffffffu, col[r], k) * ip;
                    col[r] -= mr * ck;
                }
            }
        }
        float own = 1.f;
#pragma unroll
        for (int r = 0; r < K_; ++r)
            if (r == lane) own = col[r];
        float oinv = 1.0f / own;
#pragma unroll
        for (int r = 0; r < K_; ++r) {
            float di = __shfl_sync(0xffffffffu, oinv, r);
            if (lane >= K_) s_gi[r * K_ + (lane - K_)] = col[r] * di;
        }
    }
    __syncthreads();

    float term = 0.f;
    if (tid < D_) {
        if (tid < m) {
            const int pi = s_perm[tid];
            float wv[K_], bv[K_];
            float wb = 0.f;
#pragma unroll
            for (int k4 = 0; k4 < K_; k4 += 4) {
                const float4 t4 = *reinterpret_cast<const float4*>(W + pi * K_ + k4);
                wv[k4] = t4.x; wv[k4 + 1] = t4.y; wv[k4 + 2] = t4.z; wv[k4 + 3] = t4.w;
            }
#pragma unroll
            for (int l = 0; l < K_; ++l) {
                float s = 0.f;
#pragma unroll
                for (int k = 0; k < K_; ++k) s += s_gi[l * K_ + k] * wv[k];
                bv[l] = s;
                wb += wv[l] * s;
            }
            float v = NOISEF * (1.f + wb);
#pragma unroll
            for (int k = 0; k < K_; ++k) s_B[tid * 17 + k] = bv[k];
            s_inv[tid] = 1.f / (v * (float)P_ * (float)m);
            term = (-0.5f * logf(v) - 0.5f * LOG2PI_F) / ((float)P_ * (float)m);
        } else {
#pragma unroll
            for (int k = 0; k < K_; ++k) s_B[tid * 17 + k] = 0.f;
            s_inv[tid] = 0.f;
        }
    }
    if (tid < 64) {
#pragma unroll
        for (int o = 16; o > 0; o >>= 1)
            term += __shfl_xor_sync(0xffffffffu, term, o);
        if ((tid & 31) == 0) s_red[tid >> 5] = term;
    }
    __syncthreads();
    if (tid == 0) g_part[task] = s_red[0] + s_red[1];

    // ---------------- Va/Vb: u_i = Wm b_i ----------------
    float* sVa = s_dyn;
    float* sVb = s_dyn + D_ * LST;
    {
        const int i  = tid & 63;
        const int cb = (tid >> 6) << 4;
        const int pi = s_perm[i];
        const float inv = s_inv[i];
        const float mk  = (i < m) ? 1.f : 0.f;
        float bk[K_];
#pragma unroll
        for (int k = 0; k < K_; ++k) bk[k] = s_B[i * 17 + k];
#pragma unroll
        for (int c = 0; c < 16; ++c) {
            int r = cb + c;
            float u = 0.f;
#pragma unroll
            for (int k = 0; k < K_; ++k) u += bk[k] * s_wm[r * WST + k];
            float e = (r == pi) ? 1.f : 0.f;
            sVa[i * LST + r] = (e - u) * inv;
            sVb[i * LST + r] = (e - u) * mk;
        }
    }
    __syncthreads();

    // ---------------- Lam_task = Va^T Vb, red2 -> g_Lam ----------------
    {
        const int r  = tid & 63;
        const int cb = (tid >> 6) << 4;
        float acc[16];
#pragma unroll
        for (int c = 0; c < 16; ++c) acc[c] = 0.f;
#pragma unroll
        for (int i = 0; i < D_; ++i) {
            float va = sVa[i * LST + r];
            const float4* vb4 = reinterpret_cast<const float4*>(sVb + i * LST + cb);
#pragma unroll
            for (int q = 0; q < 4; ++q) {
                float4 b4 = vb4[q];
                acc[4 * q]     += va * b4.x;
                acc[4 * q + 1] += va * b4.y;
                acc[4 * q + 2] += va * b4.z;
                acc[4 * q + 3] += va * b4.w;
            }
        }
#pragma unroll
        for (int c = 0; c < 16; c += 2)
            red2(&g_Lam[r * 64 + cb + c], acc[c], acc[c + 1]);
    }
    __threadfence();
    __syncthreads();
    if (tid == 0) {
        unsigned d = atomicAdd(&g_doneL, 1u);
        s_last = (d == (unsigned)(D_ * P_ - 1)) ? 1 : 0;
    }
    __syncthreads();
    if (!s_last) return;

    // ---------------- Finalizer: wait C, trace, output, reset ----------------
    if (tid == 0) {
        while (ld_acq(&g_done) < NBLK) __nanosleep(64);
    }
    __syncthreads();
    __threadfence();

    double trd = 0.0;
#pragma unroll
    for (int j = 0; j < 16; ++j) {
        int idx = tid + 256 * j;
        trd += (double)g_Lam[idx] * (double)g_Cf[idx];
    }
#pragma unroll
    for (int o = 16; o > 0; o >>= 1)
        trd += __shfl_xor_sync(0xffffffffu, trd, o);
    if ((tid & 31) == 0) s_tr[tid >> 5] = trd;

    double a0d = (tid < D_ * P_) ? (double)g_part[tid] : 0.0;
    if (tid < 128) {
#pragma unroll
        for (int o = 16; o > 0; o >>= 1)
            a0d += __shfl_xor_sync(0xffffffffu, a0d, o);
        if ((tid & 31) == 0) s_a0[tid >> 5] = a0d;
    }
    // reset state for next graph replay
    for (int i = tid; i < D_ * D_; i += 256) { g_Cf[i] = 0.f; g_Lam[i] = 0.f; }
    __syncthreads();
    if (tid == 0) {
        double trace = s_tr[0] + s_tr[1] + s_tr[2] + s_tr[3]
                     + s_tr[4] + s_tr[5] + s_tr[6] + s_tr[7];
        double a0    = s_a0[0] + s_a0[1] + s_a0[2] + s_a0[3];
        out[0] = (float)(0.5 / (double)N_ * trace - a0);
        g_done  = 0u;
        g_doneL = 0u;
    }
}

extern "C" void kernel_launch(void* const* d_in, const int* in_sizes, int n_in,
                              void* d_out, int out_size) {
    const float* x     = (const float*)d_in[0];
    const float* W     = (const float*)d_in[1];
    const int*   perms = (const int*)d_in[2];
    (void)in_sizes; (void)n_in; (void)out_size;

    cudaFuncSetAttribute(k_fused, cudaFuncAttributeMaxDynamicSharedMemorySize, DYNSMEM);
    k_fused<<<NBLK, 256, DYNSMEM>>>(x, W, perms, (float*)d_out);
}

// round 17
// speedup vs baseline: 2.0639x; 2.0639x over previous
#include <cuda_runtime.h>

#define D_      64
#define K_      16
#define N_      65536
#define P_      2
#define NOISEF  0.1f
#define LOG2PI_F 1.83787706640934534f

#define NBLK    296            // 2 CTAs x 148 SMs, all co-resident
#define TROWS   32
#define NPAIRS  (N_ / (2 * TROWS))   // 1024 64-row pair-tiles
#define SXST    72             // padded row stride: conflict-free fragment LDS
#define WST     20             // padded row stride for 64x16 arrays
#define PSTRIDE (2 * TROWS * SXST)   // floats per 64-row buffer (4608)
#define DYNSMEM (3 * PSTRIDE * 4)    // 55296 bytes

__device__ float    g_Cf[D_ * D_];
__device__ float    g_part[D_ * P_];
__device__ unsigned g_done;      // xtx-phase completion counter
__device__ unsigned g_done2;     // pairs-phase completion counter

__device__ __forceinline__ void cpasync16(unsigned smem, const void* g) {
    asm volatile("cp.async.cg.shared.global [%0], [%1], 16;\n" :: "r"(smem), "l"(g));
}
__device__ __forceinline__ void cp_commit() {
    asm volatile("cp.async.commit_group;\n" ::: "memory");
}
__device__ __forceinline__ void cp_wait1() {
    asm volatile("cp.async.wait_group 1;\n" ::: "memory");
}
__device__ __forceinline__ unsigned cvt_tf32(float f) {
    unsigned r;
    asm("cvt.rna.tf32.f32 %0, %1;" : "=r"(r) : "f"(f));
    return r;
}
__device__ __forceinline__ void mma_tf32(float& d0, float& d1, float& d2, float& d3,
                                         unsigned a0, unsigned a1, unsigned a2, unsigned a3,
                                         unsigned b0, unsigned b1) {
    asm("mma.sync.aligned.m16n8k8.row.col.f32.tf32.tf32.f32 "
        "{%0,%1,%2,%3}, {%4,%5,%6,%7}, {%8,%9}, {%0,%1,%2,%3};"
        : "+f"(d0), "+f"(d1), "+f"(d2), "+f"(d3)
        : "r"(a0), "r"(a1), "r"(a2), "r"(a3), "r"(b0), "r"(b1));
}
__device__ __forceinline__ unsigned ld_acq(unsigned* p) {
    unsigned v;
    asm volatile("ld.acquire.gpu.u32 %0, [%1];" : "=r"(v) : "l"(p) : "memory");
    return v;
}
__device__ __forceinline__ void red2(float* p, float a, float b) {
    asm volatile("red.global.add.v2.f32 [%0], {%1, %2};" :: "l"(p), "f"(a), "f"(b) : "memory");
}

// ---------------------------------------------------------------------------
// Fused persistent kernel — R13 pipeline verbatim, plus ONE change:
// a virtual-block remap so ALL pair blocks sit in the 3-tile stripe region
// (grid-stride blocks vb>=136 get 3 tiles, vb<136 get 4). Pair blocks
// finish phase 1 a full tile earlier, so their C-independent Woodbury prep
// genuinely overlaps the non-pair stragglers, and the device barrier is
// never gated on a 4-tile pair block.
//   pair pidx (0..127)     -> vb = 160 + pidx          (3 tiles)
//   non-pair q<136         -> vb = q                   (4 tiles)
//   non-pair q in [136,160)-> vb = q                   (3 tiles)
//   non-pair q in [160,168)-> vb = 288 + (q - 160)     (3 tiles)
// ---------------------------------------------------------------------------
__global__ __launch_bounds__(256, 2) void k_fused(const float* __restrict__ x,
                                                  const float* __restrict__ W,
                                                  const int* __restrict__ perms,
                                                  float* __restrict__ out) {
    extern __shared__ __align__(16) float s_dyn[];   // 3 x PSTRIDE (tiles) / pairs sC+sZ+sT
    __shared__ __align__(16) float s_wm[D_ * WST];
    __shared__ float s_g[K_ * K_];
    __shared__ float s_gi[K_ * K_];
    __shared__ int   s_perm[D_];
    __shared__ int   s_pos[D_];
    __shared__ float s_red[4];
    __shared__ int   s_last;

    const int tid = threadIdx.x;

    // ---------------- Virtual-block remap ----------------
    int pidx = -1;
    if (blockIdx.x < 64)                            pidx = blockIdx.x;
    else if (blockIdx.x >= 148 && blockIdx.x < 212) pidx = 64 + (blockIdx.x - 148);
    int vb;
    if (pidx >= 0) {
        vb = 160 + pidx;                       // 3-tile region
    } else {
        int q = (blockIdx.x < 148) ? (blockIdx.x - 64) : (blockIdx.x - 128);
        vb = (q < 160) ? q : 288 + (q - 160);  // q<136: 4 tiles; else 3
    }

    // ---------------- Phase 1: tf32 MMA x^T x (R13 pipeline) ----------------
    {
        const int w    = tid >> 5;
        const int lane = tid & 31;
        const int gid  = lane >> 2;       // 0..7
        const int tig  = lane & 3;        // 0..3
        const int ms   = (w >> 1) << 4;   // m-strip base: 0,16,32,48
        const int nh   = (w & 1) << 5;    // n-half base: 0,32

        float acc[4][4];
#pragma unroll
        for (int t = 0; t < 4; ++t)
#pragma unroll
            for (int q = 0; q < 4; ++q) acc[t][q] = 0.f;

        unsigned pb[3];
#pragma unroll
        for (int s = 0; s < 3; ++s)
            pb[s] = (unsigned)__cvta_generic_to_shared(&s_dyn[s * PSTRIDE]);

        // staging offsets: 1024 float4 per 64-row pair, 4 per thread
        unsigned soff[4];
#pragma unroll
        for (int i = 0; i < 4; ++i) {
            int f = tid + 256 * i;
            soff[i] = (unsigned)((f >> 4) * SXST * 4 + (f & 15) * 16);
        }

        // prologue: prefetch pairs vb, vb+NBLK into buffers 0,1
#pragma unroll
        for (int s = 0; s < 2; ++s) {
            int pr = vb + s * NBLK;
            if (pr < NPAIRS) {
                const float4* g4 = reinterpret_cast<const float4*>(x + (long long)pr * (2 * TROWS * 64));
#pragma unroll
                for (int i = 0; i < 4; ++i)
                    cpasync16(pb[s] + soff[i], g4 + tid + 256 * i);
            }
            cp_commit();
        }

        int it = 0;
        for (int pr = vb; pr < NPAIRS; pr += NBLK, ++it) {
            const int bi = it - (it / 3) * 3;   // it % 3
            cp_wait1();            // oldest group (this pair) complete
            __syncthreads();       // buffer (bi+2)%3 free; buffer bi visible

            const int nxt = pr + 2 * NBLK;
            const int nb  = (bi + 2) - ((bi + 2) / 3) * 3;
            if (nxt < NPAIRS) {
                const float4* g4 = reinterpret_cast<const float4*>(x + (long long)nxt * (2 * TROWS * 64));
#pragma unroll
                for (int i = 0; i < 4; ++i)
                    cpasync16(pb[nb] + soff[i], g4 + tid + 256 * i);
            }
            cp_commit();

            const float* buf = &s_dyn[bi * PSTRIDE];
#pragma unroll
            for (int ks = 0; ks < 8; ++ks) {
                const float* r0 = buf + (ks * 8 + tig) * SXST;
                const float* r4 = r0 + 4 * SXST;
                unsigned a0 = cvt_tf32(r0[ms + gid]);
                unsigned a1 = cvt_tf32(r0[ms + gid + 8]);
                unsigned a2 = cvt_tf32(r4[ms + gid]);
                unsigned a3 = cvt_tf32(r4[ms + gid + 8]);
#pragma unroll
                for (int t = 0; t < 4; ++t) {
                    int n0 = nh + t * 8;
                    unsigned b0 = cvt_tf32(r0[n0 + gid]);
                    unsigned b1 = cvt_tf32(r4[n0 + gid]);
                    mma_tf32(acc[t][0], acc[t][1], acc[t][2], acc[t][3],
                             a0, a1, a2, a3, b0, b1);
                }
            }
        }

        // flush accumulators (rows ms+gid / +8, cols n0+2tig / +1)
#pragma unroll
        for (int t = 0; t < 4; ++t) {
            int c0 = nh + t * 8 + 2 * tig;
            red2(&g_Cf[(ms + gid) * 64 + c0],     acc[t][0], acc[t][1]);
            red2(&g_Cf[(ms + gid + 8) * 64 + c0], acc[t][2], acc[t][3]);
        }
        __threadfence();
        __syncthreads();
        if (tid == 0) atomicAdd(&g_done, 1u);
    }

    // ---------------- Pair-task selection ----------------
    if (pidx < 0) return;
    const int task = pidx;
    const int a = task >> 1;
    const int m = a + 1;
    const int* perm = perms + (a * P_ + (task & 1)) * D_;

    // ---------------- Prep: C-independent work (overlaps stragglers) -------
    if (tid < D_) s_perm[tid] = perm[tid];
    __syncthreads();
    if (tid < D_) s_pos[s_perm[tid]] = tid;
    __syncthreads();
#pragma unroll
    for (int i = 0; i < 4; ++i) {
        int idx = tid + 256 * i;
        int o = idx >> 4, k = idx & 15;
        float wv = W[idx];
        s_wm[o * WST + k] = (s_pos[o] >= m) ? wv : 0.f;
    }
    __syncthreads();

    const int gk = tid >> 4, gl = tid & 15;
    {
        float s = (gk == gl) ? NOISEF : 0.f;
#pragma unroll
        for (int o = 0; o < D_; ++o)
            s += s_wm[o * WST + gk] * s_wm[o * WST + gl];
        s_g[gk * K_ + gl] = s;
    }
    __syncthreads();

    if (tid < 32) {
        // warp 0: shuffle Jordan inversion of 16x16 SPD G
        const int lane = tid;
        float col[K_];
#pragma unroll
        for (int r = 0; r < K_; ++r)
            col[r] = (lane < K_) ? s_g[r * K_ + lane]
                                 : ((r == lane - K_) ? 1.f : 0.f);
#pragma unroll
        for (int k = 0; k < K_; ++k) {
            float pv = __shfl_sync(0xffffffffu, col[k], k);
            float ip = 1.0f / pv;
            float ck = col[k];
#pragma unroll
            for (int r = 0; r < K_; ++r) {
                if (r != k) {
                    float mr = __shfl_sync(0xffffffffu, col[r], k) * ip;
                    col[r] -= mr * ck;
                }
            }
        }
        float own = 1.f;
#pragma unroll
        for (int r = 0; r < K_; ++r)
            if (r == lane) own = col[r];
        float oinv = 1.0f / own;
#pragma unroll
        for (int r = 0; r < K_; ++r) {
            float di = __shfl_sync(0xffffffffu, oinv, r);
            if (lane >= K_) s_gi[r * K_ + (lane - K_)] = col[r] * di;
        }
    }
    __syncthreads();

    // b = Ginv w, wb = w.b  (still C-independent)
    float bv[K_];
    float wbv = 0.f;
    if (tid < m) {
        const int pi = s_perm[tid];
        float wv[K_];
#pragma unroll
        for (int k4 = 0; k4 < K_; k4 += 4) {
            const float4 t4 = *reinterpret_cast<const float4*>(W + pi * K_ + k4);
            wv[k4] = t4.x; wv[k4 + 1] = t4.y; wv[k4 + 2] = t4.z; wv[k4 + 3] = t4.w;
        }
#pragma unroll
        for (int l = 0; l < K_; ++l) {
            float s = 0.f;
#pragma unroll
            for (int k = 0; k < K_; ++k) s += s_gi[l * K_ + k] * wv[k];
            bv[l] = s;
            wbv += wv[l] * s;
        }
    }

    // ---------------- Wait for C ----------------
    if (tid == 0) {
        while (ld_acq(&g_done) < NBLK) __nanosleep(64);
    }
    __syncthreads();     // release barrier; smem union switch

    float* sC = s_dyn;            // 64 x 65
    float* sZ = s_dyn + 4160;     // 64 x WST
    float* sT = s_dyn + 5440;     // 16 x 16

    // ---------------- C-dependent remainder ----------------
#pragma unroll
    for (int i = 0; i < 16; ++i) {
        int idx = tid + 256 * i;
        sC[(idx >> 6) * 65 + (idx & 63)] = g_Cf[idx];
    }
    __syncthreads();

    // Z = C @ Wm  (2-way split j-chains for ILP)
    {
        const int o = tid & 63, lb = (tid >> 6) << 2;
        float za0 = 0.f, za1 = 0.f, za2 = 0.f, za3 = 0.f;
        float zb0 = 0.f, zb1 = 0.f, zb2 = 0.f, zb3 = 0.f;
#pragma unroll
        for (int j = 0; j < 32; ++j) {
            float ca = sC[o * 65 + j];
            float cb = sC[o * 65 + j + 32];
            const float4 wa = *reinterpret_cast<const float4*>(s_wm + j * WST + lb);
            const float4 wb = *reinterpret_cast<const float4*>(s_wm + (j + 32) * WST + lb);
            za0 += ca * wa.x; za1 += ca * wa.y; za2 += ca * wa.z; za3 += ca * wa.w;
            zb0 += cb * wb.x; zb1 += cb * wb.y; zb2 += cb * wb.z; zb3 += cb * wb.w;
        }
        *reinterpret_cast<float4*>(sZ + o * WST + lb) =
            make_float4(za0 + zb0, za1 + zb1, za2 + zb2, za3 + zb3);
    }
    __syncthreads();

    // T = Wm^T Z : one element per thread, 4-way split o-chains
    {
        float s0 = 0.f, s1 = 0.f, s2 = 0.f, s3 = 0.f;
#pragma unroll
        for (int o = 0; o < 16; ++o) {
            s0 += s_wm[o * WST + gk]        * sZ[o * WST + gl];
            s1 += s_wm[(o + 16) * WST + gk] * sZ[(o + 16) * WST + gl];
            s2 += s_wm[(o + 32) * WST + gk] * sZ[(o + 32) * WST + gl];
            s3 += s_wm[(o + 48) * WST + gk] * sZ[(o + 48) * WST + gl];
        }
        sT[gk * K_ + gl] = (s0 + s1) + (s2 + s3);
    }
    __syncthreads();

    // per-row terms (b, wb precomputed)
    float term = 0.f;
    if (tid < m) {
        const int pi = s_perm[tid];
        float by = 0.f, btb = 0.f;
#pragma unroll
        for (int k = 0; k < K_; ++k) {
            by += bv[k] * sZ[pi * WST + k];
            float s = 0.f;
#pragma unroll
            for (int l = 0; l < K_; ++l) s += sT[k * K_ + l] * bv[l];
            btb += bv[k] * s;
        }
        float v = NOISEF * (1.f + wbv);
        float Q = sC[pi * 65 + pi] - 2.f * by + btb;
        term = -0.5f * logf(v) - 0.5f * LOG2PI_F - 0.5f * Q / (v * (float)N_);
    }
    if (tid < 64) {
#pragma unroll
        for (int o = 16; o > 0; o >>= 1)
            term += __shfl_xor_sync(0xffffffffu, term, o);
        if ((tid & 31) == 0) s_red[tid >> 5] = term;
    }
    __syncthreads();
    if (tid == 0) {
        g_part[task] = (s_red[0] + s_red[1]) / ((float)P_ * (float)m);
        __threadfence();
        unsigned d = atomicAdd(&g_done2, 1u);
        s_last = (d == (unsigned)(D_ * P_ - 1)) ? 1 : 0;
    }
    __syncthreads();

    if (s_last) {
        __threadfence();    // acquire: see all g_part stores
        float pv = (tid < D_ * P_) ? g_part[tid] : 0.f;
        if (tid < 128) {
#pragma unroll
            for (int o = 16; o > 0; o >>= 1)
                pv += __shfl_xor_sync(0xffffffffu, pv, o);
            if ((tid & 31) == 0) s_red[tid >> 5] = pv;
        }
        // reset C for the next graph replay
        for (int i = tid; i < D_ * D_; i += 256) g_Cf[i] = 0.f;
        __syncthreads();
        if (tid == 0) {
            double s = (double)s_red[0] + (double)s_red[1]
                     + (double)s_red[2] + (double)s_red[3];
            out[0] = -(float)s;
            g_done  = 0u;
            g_done2 = 0u;
        }
    }
}

extern "C" void kernel_launch(void* const* d_in, const int* in_sizes, int n_in,
                              void* d_out, int out_size) {
    const float* x     = (const float*)d_in[0];
    const float* W     = (const float*)d_in[1];
    const int*   perms = (const int*)d_in[2];
    (void)in_sizes; (void)n_in; (void)out_size;

    cudaFuncSetAttribute(k_fused, cudaFuncAttributeMaxDynamicSharedMemorySize, DYNSMEM);
    k_fused<<<NBLK, 256, DYNSMEM>>>(x, W, perms, (float*)d_out);
}